// round 2
// baseline (speedup 1.0000x reference)
#include <cuda_runtime.h>
#include <cuda_bf16.h>
#include <cstdint>
#include <cstddef>

// Problem dims (fixed)
#define NROWS 4096
#define MCOLS 4096
#define DDIM  1024

// ---------------------------------------------------------------------------
// Scratch (__device__ globals — allocation-free contract)
// ---------------------------------------------------------------------------
__device__ __nv_bfloat16 g_Hb[(size_t)NROWS * DDIM];     // H * (1/32) in bf16
__device__ __nv_bfloat16 g_Kb[(size_t)MCOLS * DDIM];     // K in bf16
__device__ __nv_bfloat16 g_Vt[(size_t)DDIM * MCOLS];     // V^T in bf16 (K-major)
__device__ float         g_scores[(size_t)NROWS * MCOLS];
__device__ __nv_bfloat16 g_e[(size_t)NROWS * MCOLS];     // expm1(p*mask) in bf16
__device__ float g_rmax[NROWS];
__device__ float g_rsum[NROWS];
__device__ float g_z[NROWS];
__device__ float g_scol[DDIM];
__device__ float g_part[32 * DDIM];

static __device__ __forceinline__ uint32_t smem_u32(const void* p) {
    uint32_t a;
    asm("{ .reg .u64 t; cvta.to.shared.u64 t, %1; cvt.u32.u64 %0, t; }"
        : "=r"(a) : "l"(p));
    return a;
}

// ---------------------------------------------------------------------------
// mma.sync bf16 GEMM (baseline ISA: ldmatrix + cp.async + HMMA.16816)
//   C[128x128 tile] = A[rowTile, :] @ B[colTile, :]^T
//   A: [*, lda] bf16 K-major; B: [*, ldb] bf16 K-major (== col-major operand)
//   mode 0: C = acc            mode 1: C = (Scol[col] + acc) / Zrow[row]
// ---------------------------------------------------------------------------
#define BM 128
#define BN 128
#define BKT 64
#define TPB 256
#define STAGES 3
#define STAGE_BYTES 32768          // 16KB A + 16KB B
#define SMEM_BYTES (STAGES * STAGE_BYTES)

static __device__ __forceinline__ uint32_t sw128(uint32_t off) {
    return off ^ ((off >> 3) & 0x70);
}

static __device__ __forceinline__ void cp16(uint32_t saddr, const void* gptr) {
    asm volatile("cp.async.cg.shared.global [%0], [%1], 16;"
                 :: "r"(saddr), "l"(gptr));
}

static __device__ __forceinline__ void cp_commit() {
    asm volatile("cp.async.commit_group;");
}

template <int N>
static __device__ __forceinline__ void cp_wait() {
    asm volatile("cp.async.wait_group %0;" :: "n"(N));
}

static __device__ __forceinline__ void ldmatrix_x4(uint32_t* r, uint32_t saddr) {
    asm volatile("ldmatrix.sync.aligned.m8n8.x4.shared.b16 {%0,%1,%2,%3}, [%4];"
                 : "=r"(r[0]), "=r"(r[1]), "=r"(r[2]), "=r"(r[3]) : "r"(saddr));
}

static __device__ __forceinline__ void mma16816(float* d, const uint32_t* a,
                                                const uint32_t* b) {
    asm volatile(
        "mma.sync.aligned.m16n8k16.row.col.f32.bf16.bf16.f32 "
        "{%0,%1,%2,%3}, {%4,%5,%6,%7}, {%8,%9}, {%0,%1,%2,%3};"
        : "+f"(d[0]), "+f"(d[1]), "+f"(d[2]), "+f"(d[3])
        : "r"(a[0]), "r"(a[1]), "r"(a[2]), "r"(a[3]), "r"(b[0]), "r"(b[1]));
}

// Issue one stage's cp.async loads: A tile 128x64 bf16 + B tile 128x64 bf16.
static __device__ __forceinline__ void issue_stage(
    const __nv_bfloat16* __restrict__ A, int lda, int rowBase,
    const __nv_bfloat16* __restrict__ B, int ldb, int colBase,
    int k0, uint32_t sbase, int tid) {
    uint32_t sA = sbase;
    uint32_t sB = sbase + 16384;
#pragma unroll
    for (int i = 0; i < 4; i++) {
        int l = tid + i * TPB;          // 0..1023 chunk id
        int r = l >> 3;                 // row 0..127
        int c = l & 7;                  // 16B chunk 0..7
        uint32_t off = sw128((uint32_t)(r * 128 + c * 16));
        cp16(sA + off, A + (size_t)(rowBase + r) * lda + k0 + c * 8);
        cp16(sB + off, B + (size_t)(colBase + r) * ldb + k0 + c * 8);
    }
}

__global__ void __launch_bounds__(TPB)
gemm_mma(const __nv_bfloat16* __restrict__ A, const __nv_bfloat16* __restrict__ B,
         int lda, int ldb, int nIter,
         float* __restrict__ C, int ldc,
         const float* __restrict__ Scol, const float* __restrict__ Zrow, int mode) {
    extern __shared__ __align__(1024) char smem[];
    uint32_t sb = smem_u32(smem);
    int tid = threadIdx.x;
    int wid = tid >> 5, lane = tid & 31;
    int wm = wid >> 1, wn = wid & 1;    // warp tile: 32 (m) x 64 (n)
    int rowBase = blockIdx.y * BM;
    int colBase = blockIdx.x * BN;

    // prologue: issue STAGES-1 stages
#pragma unroll
    for (int s = 0; s < STAGES - 1; s++) {
        issue_stage(A, lda, rowBase, B, ldb, colBase, s * BKT,
                    sb + s * STAGE_BYTES, tid);
        cp_commit();
    }

    float acc[2][8][4];
#pragma unroll
    for (int i = 0; i < 2; i++)
#pragma unroll
        for (int j = 0; j < 8; j++)
#pragma unroll
            for (int k = 0; k < 4; k++) acc[i][j][k] = 0.f;

    // precompute ldmatrix lane offsets (within a stage)
    // A: row = wm*32 + mi*16 + (lane&15), colb = ks*32 + (lane>>4)*16
    int arow = wm * 32 + (lane & 15);
    int acolb = (lane >> 4) << 4;
    // B: row = wn*64 + ni*16 + ((lane>>4)<<3) + (lane&7), colb = ks*32 + ((lane>>3)&1)*16
    int brow = wn * 64 + ((lane >> 4) << 3) + (lane & 7);
    int bcolb = ((lane >> 3) & 1) << 4;

    int stage = 0;
    for (int it = 0; it < nIter; ++it) {
        cp_wait<STAGES - 2>();
        __syncthreads();
        uint32_t baseA = sb + stage * STAGE_BYTES;
        uint32_t baseB = baseA + 16384;

#pragma unroll
        for (int ks = 0; ks < 4; ks++) {
            uint32_t af[2][4];
#pragma unroll
            for (int mi = 0; mi < 2; mi++) {
                uint32_t off = sw128((uint32_t)((arow + mi * 16) * 128 + ks * 32 + acolb));
                ldmatrix_x4(af[mi], baseA + off);
            }
            uint32_t bf[4][4];
#pragma unroll
            for (int ni = 0; ni < 4; ni++) {
                uint32_t off = sw128((uint32_t)((brow + ni * 16) * 128 + ks * 32 + bcolb));
                ldmatrix_x4(bf[ni], baseB + off);
            }
#pragma unroll
            for (int mi = 0; mi < 2; mi++)
#pragma unroll
                for (int ni = 0; ni < 4; ni++) {
                    mma16816(acc[mi][2 * ni], af[mi], &bf[ni][0]);
                    mma16816(acc[mi][2 * ni + 1], af[mi], &bf[ni][2]);
                }
        }

        int nxt = it + STAGES - 1;
        if (nxt < nIter) {
            issue_stage(A, lda, rowBase, B, ldb, colBase, nxt * BKT,
                        sb + ((nxt % STAGES) * STAGE_BYTES), tid);
        }
        cp_commit();
        stage = (stage + 1 == STAGES) ? 0 : stage + 1;
    }

    // epilogue: thread owns (m = rowBase + wm*32 + mi*16 + lane/4 + {0,8},
    //                        n = colBase + wn*64 + nj*8 + 2*(lane%4) + {0,1})
    int mrow = rowBase + wm * 32 + (lane >> 2);
    int ncol = colBase + wn * 64 + 2 * (lane & 3);
#pragma unroll
    for (int mi = 0; mi < 2; mi++) {
        int m0 = mrow + mi * 16;
        float rz0 = 1.f, rz1 = 1.f;
        if (mode == 1) {
            rz0 = 1.0f / Zrow[m0];
            rz1 = 1.0f / Zrow[m0 + 8];
        }
#pragma unroll
        for (int nj = 0; nj < 8; nj++) {
            int n = ncol + nj * 8;
            float s0 = 0.f, s1 = 0.f;
            if (mode == 1) { s0 = __ldg(Scol + n); s1 = __ldg(Scol + n + 1); }
            float2 v0, v1;
            if (mode == 0) {
                v0.x = acc[mi][nj][0]; v0.y = acc[mi][nj][1];
                v1.x = acc[mi][nj][2]; v1.y = acc[mi][nj][3];
            } else {
                v0.x = (s0 + acc[mi][nj][0]) * rz0;
                v0.y = (s1 + acc[mi][nj][1]) * rz0;
                v1.x = (s0 + acc[mi][nj][2]) * rz1;
                v1.y = (s1 + acc[mi][nj][3]) * rz1;
            }
            *reinterpret_cast<float2*>(C + (size_t)m0 * ldc + n) = v0;
            *reinterpret_cast<float2*>(C + (size_t)(m0 + 8) * ldc + n) = v1;
        }
    }
}

// ---------------------------------------------------------------------------
// Elementwise / reduction kernels
// ---------------------------------------------------------------------------
__global__ void f32_to_bf16_scaled(const float* __restrict__ src,
                                   __nv_bfloat16* __restrict__ dst,
                                   float scale, int n4) {
    int i = blockIdx.x * blockDim.x + threadIdx.x;
    if (i < n4) {
        float4 v = reinterpret_cast<const float4*>(src)[i];
        __nv_bfloat162 a = __floats2bfloat162_rn(v.x * scale, v.y * scale);
        __nv_bfloat162 b = __floats2bfloat162_rn(v.z * scale, v.w * scale);
        reinterpret_cast<__nv_bfloat162*>(dst)[2 * i] = a;
        reinterpret_cast<__nv_bfloat162*>(dst)[2 * i + 1] = b;
    }
}

__global__ void transposeV(const float* __restrict__ V, __nv_bfloat16* __restrict__ Vt) {
    __shared__ float tile[32][33];
    int d0 = blockIdx.x * 32, m0 = blockIdx.y * 32;
    int tx = threadIdx.x, ty = threadIdx.y;  // 32 x 8
#pragma unroll
    for (int j = 0; j < 32; j += 8)
        tile[ty + j][tx] = V[(size_t)(m0 + ty + j) * DDIM + d0 + tx];
    __syncthreads();
#pragma unroll
    for (int j = 0; j < 32; j += 8)
        Vt[(size_t)(d0 + ty + j) * MCOLS + m0 + tx] = __float2bfloat16_rn(tile[tx][ty + j]);
}

__global__ void colsum_partial(const float* __restrict__ V, float* __restrict__ part) {
    int d = blockIdx.x * 128 + threadIdx.x;
    int mb = blockIdx.y;
    float s = 0.f;
    for (int m = mb * 128; m < mb * 128 + 128; m++)
        s += V[(size_t)m * DDIM + d];
    part[mb * DDIM + d] = s;
}

__global__ void colsum_reduce(const float* __restrict__ part, float* __restrict__ Scol) {
    int d = blockIdx.x * blockDim.x + threadIdx.x;
    if (d < DDIM) {
        float s = 0.f;
#pragma unroll
        for (int i = 0; i < 32; i++) s += part[i * DDIM + d];
        Scol[d] = s;
    }
}

static __device__ __forceinline__ float warp_red_max(float v) {
#pragma unroll
    for (int o = 16; o > 0; o >>= 1) v = fmaxf(v, __shfl_xor_sync(0xffffffffu, v, o));
    return v;
}
static __device__ __forceinline__ float warp_red_sum(float v) {
#pragma unroll
    for (int o = 16; o > 0; o >>= 1) v += __shfl_xor_sync(0xffffffffu, v, o);
    return v;
}

__global__ void row_stats(const float* __restrict__ scores,
                          float* __restrict__ rmax, float* __restrict__ rsum) {
    __shared__ float red[8];
    __shared__ float bmax;
    int n = blockIdx.x, t = threadIdx.x;
    int wid = t >> 5, lid = t & 31;
    const float4* row = reinterpret_cast<const float4*>(scores + (size_t)n * MCOLS);
    float4 v[4];
    float mx = -1e30f;
#pragma unroll
    for (int i = 0; i < 4; i++) {
        v[i] = row[t + i * 256];
        mx = fmaxf(mx, fmaxf(fmaxf(v[i].x, v[i].y), fmaxf(v[i].z, v[i].w)));
    }
    mx = warp_red_max(mx);
    if (lid == 0) red[wid] = mx;
    __syncthreads();
    if (wid == 0) {
        float x = (lid < 8) ? red[lid] : -1e30f;
        x = warp_red_max(x);
        if (lid == 0) bmax = x;
    }
    __syncthreads();
    mx = bmax;
    float s = 0.f;
#pragma unroll
    for (int i = 0; i < 4; i++)
        s += expf(v[i].x - mx) + expf(v[i].y - mx) + expf(v[i].z - mx) + expf(v[i].w - mx);
    s = warp_red_sum(s);
    __syncthreads();
    if (lid == 0) red[wid] = s;
    __syncthreads();
    if (t == 0) {
        float acc = 0.f;
#pragma unroll
        for (int i = 0; i < 8; i++) acc += red[i];
        rmax[n] = mx;
        rsum[n] = acc;
    }
}

__global__ void build_e(const float* __restrict__ scores, const float* __restrict__ mask,
                        const float* __restrict__ rmax, const float* __restrict__ rsum,
                        __nv_bfloat16* __restrict__ e, float* __restrict__ zrow) {
    __shared__ float red[8];
    int n = blockIdx.x, t = threadIdx.x;
    int wid = t >> 5, lid = t & 31;
    const float4* srow = reinterpret_cast<const float4*>(scores + (size_t)n * MCOLS);
    const float4* mrow = reinterpret_cast<const float4*>(mask + (size_t)n * MCOLS);
    __nv_bfloat162* erow = reinterpret_cast<__nv_bfloat162*>(e + (size_t)n * MCOLS);
    float mx = rmax[n];
    float inv = 1.0f / rsum[n];
    float z = 0.f;
#pragma unroll
    for (int i = 0; i < 4; i++) {
        int idx = t + i * 256;
        float4 s = srow[idx];
        float4 m = mrow[idx];
        float e0 = expm1f(expf(s.x - mx) * inv * m.x);
        float e1 = expm1f(expf(s.y - mx) * inv * m.y);
        float e2 = expm1f(expf(s.z - mx) * inv * m.z);
        float e3 = expm1f(expf(s.w - mx) * inv * m.w);
        z += (e0 + e1) + (e2 + e3);
        erow[idx * 2] = __floats2bfloat162_rn(e0, e1);
        erow[idx * 2 + 1] = __floats2bfloat162_rn(e2, e3);
    }
    z = warp_red_sum(z);
    if (lid == 0) red[wid] = z;
    __syncthreads();
    if (t == 0) {
        float acc = 0.f;
#pragma unroll
        for (int i = 0; i < 8; i++) acc += red[i];
        zrow[n] = (float)MCOLS + acc;
    }
}

// ---------------------------------------------------------------------------
// Launch
// ---------------------------------------------------------------------------
extern "C" void kernel_launch(void* const* d_in, const int* in_sizes, int n_in,
                              void* d_out, int out_size) {
    const float* H   = (const float*)d_in[0];
    const float* K   = (const float*)d_in[1];
    const float* V   = (const float*)d_in[2];
    const float* Msk = (const float*)d_in[3];
    float* out = (float*)d_out;

    void *hb, *kb, *vt, *sc, *ee, *rm, *rs, *zz, *scol, *part;
    cudaGetSymbolAddress(&hb, g_Hb);
    cudaGetSymbolAddress(&kb, g_Kb);
    cudaGetSymbolAddress(&vt, g_Vt);
    cudaGetSymbolAddress(&sc, g_scores);
    cudaGetSymbolAddress(&ee, g_e);
    cudaGetSymbolAddress(&rm, g_rmax);
    cudaGetSymbolAddress(&rs, g_rsum);
    cudaGetSymbolAddress(&zz, g_z);
    cudaGetSymbolAddress(&scol, g_scol);
    cudaGetSymbolAddress(&part, g_part);

    cudaFuncSetAttribute(gemm_mma, cudaFuncAttributeMaxDynamicSharedMemorySize,
                         SMEM_BYTES);

    // Stage 0: bf16 conversions (H pre-scaled by 1/sqrt(D) = 1/32)
    f32_to_bf16_scaled<<<4096, 256>>>(H, (__nv_bfloat16*)hb, 1.0f / 32.0f,
                                      NROWS * DDIM / 4);
    f32_to_bf16_scaled<<<4096, 256>>>(K, (__nv_bfloat16*)kb, 1.0f, MCOLS * DDIM / 4);
    transposeV<<<dim3(DDIM / 32, MCOLS / 32), dim3(32, 8)>>>(V, (__nv_bfloat16*)vt);
    colsum_partial<<<dim3(DDIM / 128, 32), 128>>>(V, (float*)part);
    colsum_reduce<<<DDIM / 256, 256>>>((const float*)part, (float*)scol);

    // Stage 1: scores = (H/32) @ K^T  (fp32 out)
    gemm_mma<<<dim3(MCOLS / BN, NROWS / BM), TPB, SMEM_BYTES>>>(
        (const __nv_bfloat16*)hb, (const __nv_bfloat16*)kb, DDIM, DDIM, DDIM / BKT,
        (float*)sc, MCOLS, nullptr, nullptr, 0);

    // Stage 2: row softmax stats; e = expm1(softmax * mask); z = M + sum(e)
    row_stats<<<NROWS, 256>>>((const float*)sc, (float*)rm, (float*)rs);
    build_e<<<NROWS, 256>>>((const float*)sc, Msk, (const float*)rm, (const float*)rs,
                            (__nv_bfloat16*)ee, (float*)zz);

    // Stage 3: out = (colsum(V) + e @ V) / z
    gemm_mma<<<dim3(DDIM / BN, NROWS / BM), TPB, SMEM_BYTES>>>(
        (const __nv_bfloat16*)ee, (const __nv_bfloat16*)vt, MCOLS, MCOLS, MCOLS / BKT,
        out, DDIM, (const float*)scol, (const float*)zz, 1);
}

// round 5
// speedup vs baseline: 1.5148x; 1.5148x over previous
#include <cuda_runtime.h>
#include <cuda_bf16.h>
#include <cstdint>
#include <cstddef>

// Problem dims (fixed)
#define NROWS 4096
#define MCOLS 4096
#define DDIM  1024

// ---------------------------------------------------------------------------
// Scratch (__device__ globals — allocation-free contract)
// ---------------------------------------------------------------------------
__device__ __nv_bfloat16 g_Hb[(size_t)NROWS * DDIM];     // H * (1/32) in bf16
__device__ __nv_bfloat16 g_Kb[(size_t)MCOLS * DDIM];     // K in bf16
__device__ __nv_bfloat16 g_Vt[(size_t)DDIM * MCOLS];     // V^T in bf16 (K-major)
__device__ __nv_bfloat16 g_expsc[(size_t)NROWS * MCOLS]; // exp(scores) bf16
__device__ __nv_bfloat16 g_e[(size_t)NROWS * MCOLS];     // expm1(p*mask) bf16
__device__ float g_rsum[NROWS];
__device__ float g_z[NROWS];
__device__ float g_scol[DDIM];
__device__ float g_part[64 * NROWS];   // GEMM1 partial row sums (32 tiles x 2 warps)
__device__ float g_partc[32 * DDIM];   // colsum partials

static __device__ __forceinline__ uint32_t smem_u32(const void* p) {
    uint32_t a;
    asm("{ .reg .u64 t; cvta.to.shared.u64 t, %1; cvt.u32.u64 %0, t; }"
        : "=r"(a) : "l"(p));
    return a;
}

// ---------------------------------------------------------------------------
// mma.sync bf16 GEMM (ldmatrix + cp.async + HMMA.16816)
//   C tile = A[rowTile, :] @ B[colTile, :]^T
//   mode 2: expsc[n] = bf16(exp(acc)); partial row sums -> part
//   mode 1: C = (Scol[col] + acc) / Zrow[row]   (fp32 out)
// ---------------------------------------------------------------------------
#define BM 128
#define BN 128
#define BKT 64
#define TPB 256
#define STAGES 3
#define STAGE_BYTES 32768          // 16KB A + 16KB B
#define SMEM_BYTES (STAGES * STAGE_BYTES)

static __device__ __forceinline__ uint32_t sw128(uint32_t off) {
    return off ^ ((off >> 3) & 0x70);
}

static __device__ __forceinline__ void cp16(uint32_t saddr, const void* gptr) {
    asm volatile("cp.async.cg.shared.global [%0], [%1], 16;"
                 :: "r"(saddr), "l"(gptr));
}

static __device__ __forceinline__ void cp_commit() {
    asm volatile("cp.async.commit_group;");
}

template <int N>
static __device__ __forceinline__ void cp_wait() {
    asm volatile("cp.async.wait_group %0;" :: "n"(N));
}

static __device__ __forceinline__ void ldmatrix_x4(uint32_t* r, uint32_t saddr) {
    asm volatile("ldmatrix.sync.aligned.m8n8.x4.shared.b16 {%0,%1,%2,%3}, [%4];"
                 : "=r"(r[0]), "=r"(r[1]), "=r"(r[2]), "=r"(r[3]) : "r"(saddr));
}

static __device__ __forceinline__ void mma16816(float* d, const uint32_t* a,
                                                const uint32_t* b) {
    asm volatile(
        "mma.sync.aligned.m16n8k16.row.col.f32.bf16.bf16.f32 "
        "{%0,%1,%2,%3}, {%4,%5,%6,%7}, {%8,%9}, {%0,%1,%2,%3};"
        : "+f"(d[0]), "+f"(d[1]), "+f"(d[2]), "+f"(d[3])
        : "r"(a[0]), "r"(a[1]), "r"(a[2]), "r"(a[3]), "r"(b[0]), "r"(b[1]));
}

static __device__ __forceinline__ void issue_stage(
    const __nv_bfloat16* __restrict__ A, int lda, int rowBase,
    const __nv_bfloat16* __restrict__ B, int ldb, int colBase,
    int k0, uint32_t sbase, int tid) {
    uint32_t sA = sbase;
    uint32_t sB = sbase + 16384;
#pragma unroll
    for (int i = 0; i < 4; i++) {
        int l = tid + i * TPB;          // 0..1023 chunk id
        int r = l >> 3;                 // row 0..127
        int c = l & 7;                  // 16B chunk 0..7
        uint32_t off = sw128((uint32_t)(r * 128 + c * 16));
        cp16(sA + off, A + (size_t)(rowBase + r) * lda + k0 + c * 8);
        cp16(sB + off, B + (size_t)(colBase + r) * ldb + k0 + c * 8);
    }
}

__global__ void __launch_bounds__(TPB)
gemm_mma(const __nv_bfloat16* __restrict__ A, const __nv_bfloat16* __restrict__ B,
         int lda, int ldb, int nIter,
         float* __restrict__ C, __nv_bfloat16* __restrict__ Cb,
         float* __restrict__ part, int ldc,
         const float* __restrict__ Scol, const float* __restrict__ Zrow, int mode) {
    extern __shared__ __align__(1024) char smem[];
    uint32_t sb = smem_u32(smem);
    int tid = threadIdx.x;
    int wid = tid >> 5, lane = tid & 31;
    int wm = wid >> 1, wn = wid & 1;    // warp tile: 32 (m) x 64 (n)
    int rowBase = blockIdx.y * BM;
    int colBase = blockIdx.x * BN;

#pragma unroll
    for (int s = 0; s < STAGES - 1; s++) {
        issue_stage(A, lda, rowBase, B, ldb, colBase, s * BKT,
                    sb + s * STAGE_BYTES, tid);
        cp_commit();
    }

    float acc[2][8][4];
#pragma unroll
    for (int i = 0; i < 2; i++)
#pragma unroll
        for (int j = 0; j < 8; j++)
#pragma unroll
            for (int k = 0; k < 4; k++) acc[i][j][k] = 0.f;

    int arow = wm * 32 + (lane & 15);
    int acolb = (lane >> 4) << 4;
    int brow = wn * 64 + ((lane >> 4) << 3) + (lane & 7);
    int bcolb = ((lane >> 3) & 1) << 4;

    int stage = 0;
    for (int it = 0; it < nIter; ++it) {
        cp_wait<STAGES - 2>();
        __syncthreads();
        uint32_t baseA = sb + stage * STAGE_BYTES;
        uint32_t baseB = baseA + 16384;

#pragma unroll
        for (int ks = 0; ks < 4; ks++) {
            uint32_t af[2][4];
#pragma unroll
            for (int mi = 0; mi < 2; mi++) {
                uint32_t off = sw128((uint32_t)((arow + mi * 16) * 128 + ks * 32 + acolb));
                ldmatrix_x4(af[mi], baseA + off);
            }
            uint32_t bf[4][4];
#pragma unroll
            for (int ni = 0; ni < 4; ni++) {
                uint32_t off = sw128((uint32_t)((brow + ni * 16) * 128 + ks * 32 + bcolb));
                ldmatrix_x4(bf[ni], baseB + off);
            }
#pragma unroll
            for (int mi = 0; mi < 2; mi++)
#pragma unroll
                for (int ni = 0; ni < 4; ni++) {
                    mma16816(acc[mi][2 * ni], af[mi], &bf[ni][0]);
                    mma16816(acc[mi][2 * ni + 1], af[mi], &bf[ni][2]);
                }
        }

        int nxt = it + STAGES - 1;
        if (nxt < nIter) {
            issue_stage(A, lda, rowBase, B, ldb, colBase, nxt * BKT,
                        sb + ((nxt % STAGES) * STAGE_BYTES), tid);
        }
        cp_commit();
        stage = (stage + 1 == STAGES) ? 0 : stage + 1;
    }

    int mrow = rowBase + wm * 32 + (lane >> 2);
    int ncol = colBase + wn * 64 + 2 * (lane & 3);

    if (mode == 2) {
        // expsc = bf16(exp(acc)); deterministic partial row sums.
#pragma unroll
        for (int mi = 0; mi < 2; mi++) {
            int m0 = mrow + mi * 16;
            float s0 = 0.f, s1 = 0.f;
#pragma unroll
            for (int nj = 0; nj < 8; nj++) {
                int n = ncol + nj * 8;
                float e00 = __expf(acc[mi][nj][0]);  // fast exp: rel err ~1e-6, fine
                float e01 = __expf(acc[mi][nj][1]);
                float e10 = __expf(acc[mi][nj][2]);
                float e11 = __expf(acc[mi][nj][3]);
                s0 += e00 + e01;
                s1 += e10 + e11;
                *reinterpret_cast<__nv_bfloat162*>(Cb + (size_t)m0 * ldc + n) =
                    __floats2bfloat162_rn(e00, e01);
                *reinterpret_cast<__nv_bfloat162*>(Cb + (size_t)(m0 + 8) * ldc + n) =
                    __floats2bfloat162_rn(e10, e11);
            }
            // reduce over the 4 lanes sharing each row (fixed order: xor1 then xor2)
            s0 += __shfl_xor_sync(0xffffffffu, s0, 1);
            s0 += __shfl_xor_sync(0xffffffffu, s0, 2);
            s1 += __shfl_xor_sync(0xffffffffu, s1, 1);
            s1 += __shfl_xor_sync(0xffffffffu, s1, 2);
            if ((lane & 3) == 0) {
                int slot = blockIdx.x * 2 + wn;
                part[(size_t)slot * NROWS + m0]     = s0;
                part[(size_t)slot * NROWS + m0 + 8] = s1;
            }
        }
    } else {
        // mode 1: out = (Scol + acc) / z
#pragma unroll
        for (int mi = 0; mi < 2; mi++) {
            int m0 = mrow + mi * 16;
            float rz0 = 1.0f / Zrow[m0];
            float rz1 = 1.0f / Zrow[m0 + 8];
#pragma unroll
            for (int nj = 0; nj < 8; nj++) {
                int n = ncol + nj * 8;
                float s0 = __ldg(Scol + n), s1 = __ldg(Scol + n + 1);
                float2 v0, v1;
                v0.x = (s0 + acc[mi][nj][0]) * rz0;
                v0.y = (s1 + acc[mi][nj][1]) * rz0;
                v1.x = (s0 + acc[mi][nj][2]) * rz1;
                v1.y = (s1 + acc[mi][nj][3]) * rz1;
                *reinterpret_cast<float2*>(C + (size_t)m0 * ldc + n) = v0;
                *reinterpret_cast<float2*>(C + (size_t)(m0 + 8) * ldc + n) = v1;
            }
        }
    }
}

// ---------------------------------------------------------------------------
// Elementwise / reduction kernels
// ---------------------------------------------------------------------------
__global__ void conv_HK(const float* __restrict__ H, const float* __restrict__ K,
                        __nv_bfloat16* __restrict__ Hb, __nv_bfloat16* __restrict__ Kb) {
    const int n4 = NROWS * DDIM / 4;   // float4 count per tensor
    int i = blockIdx.x * blockDim.x + threadIdx.x;
    const float* src;
    __nv_bfloat16* dst;
    float scale;
    if (i < n4) { src = H; dst = Hb; scale = 1.0f / 32.0f; }
    else        { src = K; dst = Kb; scale = 1.0f; i -= n4; }
    float4 v = reinterpret_cast<const float4*>(src)[i];
    __nv_bfloat162 a = __floats2bfloat162_rn(v.x * scale, v.y * scale);
    __nv_bfloat162 b = __floats2bfloat162_rn(v.z * scale, v.w * scale);
    reinterpret_cast<__nv_bfloat162*>(dst)[2 * i] = a;
    reinterpret_cast<__nv_bfloat162*>(dst)[2 * i + 1] = b;
}

__global__ void transposeV(const float* __restrict__ V, __nv_bfloat16* __restrict__ Vt) {
    __shared__ float tile[32][33];
    int d0 = blockIdx.x * 32, m0 = blockIdx.y * 32;
    int tx = threadIdx.x, ty = threadIdx.y;  // 32 x 8
#pragma unroll
    for (int j = 0; j < 32; j += 8)
        tile[ty + j][tx] = V[(size_t)(m0 + ty + j) * DDIM + d0 + tx];
    __syncthreads();
#pragma unroll
    for (int j = 0; j < 32; j += 8)
        Vt[(size_t)(d0 + ty + j) * MCOLS + m0 + tx] = __float2bfloat16_rn(tile[tx][ty + j]);
}

__global__ void colsum_partial(const float* __restrict__ V, float* __restrict__ part) {
    int d = blockIdx.x * 256 + threadIdx.x;
    int mb = blockIdx.y;                       // 128 rows per block
    const float* p = V + (size_t)mb * 128 * DDIM + d;
    float s0 = 0.f, s1 = 0.f, s2 = 0.f, s3 = 0.f;
#pragma unroll 8
    for (int m = 0; m < 128; m += 4) {
        s0 += p[(size_t)m * DDIM];
        s1 += p[(size_t)(m + 1) * DDIM];
        s2 += p[(size_t)(m + 2) * DDIM];
        s3 += p[(size_t)(m + 3) * DDIM];
    }
    part[mb * DDIM + d] = (s0 + s1) + (s2 + s3);
}

__global__ void colsum_reduce(const float* __restrict__ part, float* __restrict__ Scol) {
    int d = blockIdx.x * blockDim.x + threadIdx.x;
    if (d < DDIM) {
        float s = 0.f;
#pragma unroll
        for (int i = 0; i < 32; i++) s += part[i * DDIM + d];
        Scol[d] = s;
    }
}

__global__ void reduce_rsum(const float* __restrict__ part, float* __restrict__ rsum) {
    int r = blockIdx.x * 256 + threadIdx.x;
    float s = 0.f;
#pragma unroll
    for (int j = 0; j < 64; j++) s += part[(size_t)j * NROWS + r];
    rsum[r] = s;
}

static __device__ __forceinline__ float warp_red_sum(float v) {
#pragma unroll
    for (int o = 16; o > 0; o >>= 1) v += __shfl_xor_sync(0xffffffffu, v, o);
    return v;
}

__global__ void build_e(const __nv_bfloat16* __restrict__ expsc,
                        const float* __restrict__ mask,
                        const float* __restrict__ rsum,
                        __nv_bfloat16* __restrict__ e, float* __restrict__ zrow) {
    __shared__ float red[8];
    int n = blockIdx.x, t = threadIdx.x;
    int wid = t >> 5, lid = t & 31;
    const __nv_bfloat162* srow =
        reinterpret_cast<const __nv_bfloat162*>(expsc + (size_t)n * MCOLS);
    const float4* mrow = reinterpret_cast<const float4*>(mask + (size_t)n * MCOLS);
    __nv_bfloat162* erow = reinterpret_cast<__nv_bfloat162*>(e + (size_t)n * MCOLS);
    float inv = 1.0f / rsum[n];
    float z = 0.f;
#pragma unroll
    for (int i = 0; i < 4; i++) {
        int idx = t + i * 256;
        float4 m = mrow[idx];
        __nv_bfloat162 p0 = srow[2 * idx];
        __nv_bfloat162 p1 = srow[2 * idx + 1];
        float e0 = expm1f(__low2float(p0)  * inv * m.x);
        float e1 = expm1f(__high2float(p0) * inv * m.y);
        float e2 = expm1f(__low2float(p1)  * inv * m.z);
        float e3 = expm1f(__high2float(p1) * inv * m.w);
        z += (e0 + e1) + (e2 + e3);
        erow[idx * 2] = __floats2bfloat162_rn(e0, e1);
        erow[idx * 2 + 1] = __floats2bfloat162_rn(e2, e3);
    }
    z = warp_red_sum(z);
    if (lid == 0) red[wid] = z;
    __syncthreads();
    if (t == 0) {
        float acc = 0.f;
#pragma unroll
        for (int i = 0; i < 8; i++) acc += red[i];
        zrow[n] = (float)MCOLS + acc;
    }
}

// ---------------------------------------------------------------------------
// Launch
// ---------------------------------------------------------------------------
extern "C" void kernel_launch(void* const* d_in, const int* in_sizes, int n_in,
                              void* d_out, int out_size) {
    const float* H   = (const float*)d_in[0];
    const float* K   = (const float*)d_in[1];
    const float* V   = (const float*)d_in[2];
    const float* Msk = (const float*)d_in[3];
    float* out = (float*)d_out;

    void *hb, *kb, *vt, *es, *ee, *rs, *zz, *scol, *part, *partc;
    cudaGetSymbolAddress(&hb, g_Hb);
    cudaGetSymbolAddress(&kb, g_Kb);
    cudaGetSymbolAddress(&vt, g_Vt);
    cudaGetSymbolAddress(&es, g_expsc);
    cudaGetSymbolAddress(&ee, g_e);
    cudaGetSymbolAddress(&rs, g_rsum);
    cudaGetSymbolAddress(&zz, g_z);
    cudaGetSymbolAddress(&scol, g_scol);
    cudaGetSymbolAddress(&part, g_part);
    cudaGetSymbolAddress(&partc, g_partc);

    cudaFuncSetAttribute(gemm_mma, cudaFuncAttributeMaxDynamicSharedMemorySize,
                         SMEM_BYTES);

    // Stage 0: bf16 conversions (H pre-scaled by 1/sqrt(D) = 1/32) + V prep
    conv_HK<<<2 * (NROWS * DDIM / 4) / 256, 256>>>(H, K, (__nv_bfloat16*)hb,
                                                   (__nv_bfloat16*)kb);
    transposeV<<<dim3(DDIM / 32, MCOLS / 32), dim3(32, 8)>>>(V, (__nv_bfloat16*)vt);
    colsum_partial<<<dim3(DDIM / 256, 32), 256>>>(V, (float*)partc);
    colsum_reduce<<<DDIM / 256, 256>>>((const float*)partc, (float*)scol);

    // Stage 1: expsc = bf16(exp(H/32 @ K^T)) + partial row sums (fused epilogue)
    gemm_mma<<<dim3(MCOLS / BN, NROWS / BM), TPB, SMEM_BYTES>>>(
        (const __nv_bfloat16*)hb, (const __nv_bfloat16*)kb, DDIM, DDIM, DDIM / BKT,
        nullptr, (__nv_bfloat16*)es, (float*)part, MCOLS, nullptr, nullptr, 2);
    reduce_rsum<<<NROWS / 256, 256>>>((const float*)part, (float*)rs);

    // Stage 2: e = expm1(softmax1 * mask) bf16; z = M + sum(e)
    build_e<<<NROWS, 256>>>((const __nv_bfloat16*)es, Msk, (const float*)rs,
                            (__nv_bfloat16*)ee, (float*)zz);

    // Stage 3: out = (colsum(V) + e @ V) / z
    gemm_mma<<<dim3(DDIM / BN, NROWS / BM), TPB, SMEM_BYTES>>>(
        (const __nv_bfloat16*)ee, (const __nv_bfloat16*)vt, MCOLS, MCOLS, MCOLS / BKT,
        out, nullptr, nullptr, DDIM, (const float*)scol, (const float*)zz, 1);
}